// round 13
// baseline (speedup 1.0000x reference)
#include <cuda_runtime.h>
#include <cstdint>
#include <cstddef>

#define Bb 16
#define MMAX 64

// ---------------- device scratch (allocation-free rule) ----------------
__device__ __align__(16) float g_WvWq[512 * 256];
__device__ __align__(16) float g_ivq[256];
__device__ __align__(16) float g_base[Bb * 256];
__device__ __align__(16) float g_hpart[Bb * 4 * 256];
__device__ __align__(16) float g_kproj[Bb * 256 * 256];
__device__ __align__(16) float g_Gbot[Bb * 256 * 256];
__device__ __align__(16) float g_gumbel[Bb * MMAX * 256];

// ---------------- XLA/Eigen rational tanh -------------------------------
__device__ __forceinline__ float tanh_xla(float x) {
    float xc = fminf(fmaxf(x, -9.0f), 9.0f);
    float s = xc * xc;
    float p = -2.76076847742355e-16f;
    p = fmaf(p, s, 2.00018790482477e-13f);
    p = fmaf(p, s, -8.60467152213735e-11f);
    p = fmaf(p, s, 5.12229709037114e-08f);
    p = fmaf(p, s, 1.48572235717979e-05f);
    p = fmaf(p, s, 6.37261928875436e-04f);
    p = fmaf(p, s, 4.89352455891786e-03f);
    p = p * xc;
    float q = 1.19825839466702e-06f;
    q = fmaf(q, s, 1.18534705686654e-04f);
    q = fmaf(q, s, 2.26843463243900e-03f);
    q = fmaf(q, s, 4.89352518554385e-03f);
    float r0;
    asm("rcp.approx.f32 %0, %1;" : "=f"(r0) : "f"(q));
    r0 = r0 * fmaf(-q, r0, 2.0f);            // Newton -> ~fp32 exact
    return p * r0;
}

// fast version (rcp.approx only, rel err ~1.6e-7) for the phase-A dot
__device__ __forceinline__ float tanh_fast(float x) {
    float xc = fminf(fmaxf(x, -9.0f), 9.0f);
    float s = xc * xc;
    float p = -2.76076847742355e-16f;
    p = fmaf(p, s, 2.00018790482477e-13f);
    p = fmaf(p, s, -8.60467152213735e-11f);
    p = fmaf(p, s, 5.12229709037114e-08f);
    p = fmaf(p, s, 1.48572235717979e-05f);
    p = fmaf(p, s, 6.37261928875436e-04f);
    p = fmaf(p, s, 4.89352455891786e-03f);
    p = p * xc;
    float q = 1.19825839466702e-06f;
    q = fmaf(q, s, 1.18534705686654e-04f);
    q = fmaf(q, s, 2.26843463243900e-03f);
    q = fmaf(q, s, 4.89352518554385e-03f);
    float r0;
    asm("rcp.approx.f32 %0, %1;" : "=f"(r0) : "f"(q));
    return p * r0;
}

// ---------------- threefry2x32 (JAX schedule) ---------------------------
__device__ __forceinline__ uint32_t rotl32(uint32_t v, int d) {
    return (v << d) | (v >> (32 - d));
}
__device__ __forceinline__ void threefry2x32(uint32_t k0, uint32_t k1,
                                             uint32_t x0, uint32_t x1,
                                             uint32_t& o0, uint32_t& o1) {
    uint32_t k2 = k0 ^ k1 ^ 0x1BD11BDAu;
    x0 += k0; x1 += k1;
#define TFR(r) { x0 += x1; x1 = rotl32(x1, r); x1 ^= x0; }
    TFR(13) TFR(15) TFR(26) TFR(6)   x0 += k1; x1 += k2 + 1u;
    TFR(17) TFR(29) TFR(16) TFR(24)  x0 += k2; x1 += k0 + 2u;
    TFR(13) TFR(15) TFR(26) TFR(6)   x0 += k0; x1 += k1 + 3u;
    TFR(17) TFR(29) TFR(16) TFR(24)  x0 += k1; x1 += k2 + 4u;
    TFR(13) TFR(15) TFR(26) TFR(6)   x0 += k2; x1 += k0 + 5u;
#undef TFR
    o0 = x0; o1 = x1;
}

// ---------------- cluster / DSMEM helpers -------------------------------
#define CLUSTER_SYNC() do { \
    asm volatile("barrier.cluster.arrive.aligned;" ::: "memory"); \
    asm volatile("barrier.cluster.wait.aligned;"   ::: "memory"); } while (0)

__device__ __forceinline__ uint32_t smem_u32(const void* p) {
    return (uint32_t)__cvta_generic_to_shared(p);
}
__device__ __forceinline__ uint32_t mapa_rank(uint32_t saddr, uint32_t r) {
    uint32_t o;
    asm("mapa.shared::cluster.u32 %0, %1, %2;" : "=r"(o) : "r"(saddr), "r"(r));
    return o;
}
__device__ __forceinline__ void st_cluster_b64(uint32_t addr, uint64_t v) {
    asm volatile("st.shared::cluster.b64 [%0], %1;" :: "r"(addr), "l"(v));
}
__device__ __forceinline__ void st_cluster_rel_b64(uint32_t addr, uint64_t v) {
    asm volatile("st.release.cluster.shared::cluster.b64 [%0], %1;"
                 :: "r"(addr), "l"(v) : "memory");
}
__device__ __forceinline__ uint32_t ld_acq_shared_b32(uint32_t addr) {
    uint32_t v;
    asm volatile("ld.acquire.cluster.shared::cta.b32 %0, [%1];"
                 : "=r"(v) : "r"(addr) : "memory");
    return v;
}
__device__ __forceinline__ uint64_t pack2(float a, float b) {
    return (uint64_t)__float_as_uint(a) | ((uint64_t)__float_as_uint(b) << 32);
}

// ---------------- profile-alignment dummy (shifts ncu -s5 onto decode) --
__global__ void dummy_kernel() {}

// ---------------- 64x64 tiled GEMM (BK=16, 256 thr, 4x4 micro) ----------
__device__ __forceinline__ void gemm64(const float* __restrict__ A,
                                       const float* __restrict__ B,
                                       float* __restrict__ C,
                                       int K, int N, int bx, int by) {
    __shared__ __align__(16) float As[16][68];
    __shared__ __align__(16) float Bs[16][68];
    int t = threadIdx.x;
    int tx = t & 15, ty = t >> 4;
    int row0 = by * 64, col0 = bx * 64;
    int am = t >> 2, akc = (t & 3) * 4;
    int bk = t >> 4, bnc = (t & 15) * 4;
    float acc[4][4];
#pragma unroll
    for (int u = 0; u < 4; u++)
#pragma unroll
        for (int v = 0; v < 4; v++) acc[u][v] = 0.0f;

    for (int k0 = 0; k0 < K; k0 += 16) {
        float4 av = *(const float4*)(A + (size_t)(row0 + am) * K + k0 + akc);
        As[akc + 0][am] = av.x; As[akc + 1][am] = av.y;
        As[akc + 2][am] = av.z; As[akc + 3][am] = av.w;
        *(float4*)&Bs[bk][bnc] =
            *(const float4*)(B + (size_t)(k0 + bk) * N + col0 + bnc);
        __syncthreads();
#pragma unroll
        for (int kk = 0; kk < 16; kk++) {
            float4 a  = *(const float4*)&As[kk][ty * 4];
            float4 bb = *(const float4*)&Bs[kk][tx * 4];
            acc[0][0] = fmaf(a.x, bb.x, acc[0][0]);
            acc[0][1] = fmaf(a.x, bb.y, acc[0][1]);
            acc[0][2] = fmaf(a.x, bb.z, acc[0][2]);
            acc[0][3] = fmaf(a.x, bb.w, acc[0][3]);
            acc[1][0] = fmaf(a.y, bb.x, acc[1][0]);
            acc[1][1] = fmaf(a.y, bb.y, acc[1][1]);
            acc[1][2] = fmaf(a.y, bb.z, acc[1][2]);
            acc[1][3] = fmaf(a.y, bb.w, acc[1][3]);
            acc[2][0] = fmaf(a.z, bb.x, acc[2][0]);
            acc[2][1] = fmaf(a.z, bb.y, acc[2][1]);
            acc[2][2] = fmaf(a.z, bb.z, acc[2][2]);
            acc[2][3] = fmaf(a.z, bb.w, acc[2][3]);
            acc[3][0] = fmaf(a.w, bb.x, acc[3][0]);
            acc[3][1] = fmaf(a.w, bb.y, acc[3][1]);
            acc[3][2] = fmaf(a.w, bb.z, acc[3][2]);
            acc[3][3] = fmaf(a.w, bb.w, acc[3][3]);
        }
        __syncthreads();
    }
#pragma unroll
    for (int u = 0; u < 4; u++) {
        float4 o = make_float4(acc[u][0], acc[u][1], acc[u][2], acc[u][3]);
        *(float4*)(C + (size_t)(row0 + ty * 4 + u) * N + col0 + tx * 4) = o;
    }
}

// ---------------- K1: WvWq tiles + mean-partials + gumbel (flat) --------
__global__ void k1_kernel(const float* __restrict__ Wv,
                          const float* __restrict__ Wq,
                          const float* __restrict__ emb) {
    int bid = blockIdx.x;
    if (bid < 32) {
        gemm64(Wv, Wq, g_WvWq, 256, 256, bid & 3, bid >> 2);
    } else if (bid < 96) {
        int id = bid - 32, b = id >> 2, qq = id & 3;
        const float* E = emb + ((size_t)b * 256 + qq * 64) * 256;
        int e = threadIdx.x;
        float a0 = 0, a1 = 0, a2 = 0, a3 = 0;
        for (int r = 0; r < 64; r += 4) {
            a0 += E[(size_t)(r + 0) * 256 + e];
            a1 += E[(size_t)(r + 1) * 256 + e];
            a2 += E[(size_t)(r + 2) * 256 + e];
            a3 += E[(size_t)(r + 3) * 256 + e];
        }
        g_hpart[((b * 4 + qq) << 8) + e] = (a0 + a1) + (a2 + a3);
    } else {
        int pair = bid - 96;                 // 0..1023
        int b = pair >> 6, i = pair & 63;
        int j = threadIdx.x;
        uint32_t b0, b1, s0, s1, o0, o1;
        threefry2x32(0u, 42u, 0u, (uint32_t)b, b0, b1);
        threefry2x32(b0, b1, 0u, (uint32_t)i, s0, s1);
        threefry2x32(s0, s1, 0u, (uint32_t)j, o0, o1);
        uint32_t bits = o0 ^ o1;
        float f = __uint_as_float((bits >> 9) | 0x3F800000u) - 1.0f;
        float u = fmaxf(1.17549435e-38f, f);
        g_gumbel[((size_t)b * MMAX + i) * 256 + j] = -logf(-logf(u));
    }
}

// ---------------- K2: kproj+Gbot GEMMs + ivq + base finalize ------------
__global__ void k2_kernel(const float* __restrict__ emb,
                          const float* __restrict__ Wk,
                          const float* __restrict__ init_w,
                          const float* __restrict__ Whc,
                          const float* __restrict__ bhc,
                          const float* __restrict__ bv,
                          const float* __restrict__ Wq) {
    int bid = blockIdx.x;
    if (bid < 512) {
        int item = bid >> 5;
        int r = bid & 31, mat = r >> 4, tile = r & 15;
        const float* A = emb + (size_t)item * 65536;
        const float* B = mat ? (g_WvWq + 65536) : Wk;   // Gbot uses Wv bottom half
        float* C = (mat ? g_Gbot : g_kproj) + (size_t)item * 65536;
        gemm64(A, B, C, 256, 256, tile & 3, tile >> 2);
    } else if (bid == 512) {
        int h = threadIdx.x;
        float a = 0.0f;
        for (int k = 0; k < 512; k++) a = fmaf(init_w[k], g_WvWq[k * 256 + h], a);
        g_ivq[h] = a;
    } else {
        int b = bid - 513;
        __shared__ __align__(16) float sh[256];
        __shared__ __align__(16) float st1[256];
        int e = threadIdx.x;
        float hb = (g_hpart[(b * 4 + 0) * 256 + e] + g_hpart[(b * 4 + 1) * 256 + e]
                  + g_hpart[(b * 4 + 2) * 256 + e] + g_hpart[(b * 4 + 3) * 256 + e])
                  * (1.0f / 256.0f);
        sh[e] = hb;
        __syncthreads();
        float a = 0.0f;
        for (int k = 0; k < 256; k++) a = fmaf(sh[k], Whc[k * 256 + e], a);
        st1[e] = a + bhc[e] + bv[e];
        __syncthreads();
        float a2 = 0.0f;
        for (int k = 0; k < 256; k++) a2 = fmaf(st1[k], Wq[k * 256 + e], a2);
        g_base[b * 256 + e] = a2;
    }
}

// ---------------- decode: 8-CTA cluster, tagged DSMEM exchange ----------
// slot layout per rank: [sc, sl, ex, tagword]; tagword = gidx | (step+1)<<16
__global__ void __cluster_dims__(8, 1, 1) __launch_bounds__(512, 1)
decode_kernel(const float* __restrict__ node, const float* __restrict__ costs,
              const float* __restrict__ vptr, const float* __restrict__ emb,
              float* __restrict__ out) {
    __shared__ __align__(16) float s_qbase[256];
    __shared__ __align__(16) float s_u[32];
    __shared__ __align__(16) float s_slots[2][8][4];   // [buf][rank][sc,sl,ex,tag]
    __shared__ __align__(16) float s_node[1024];
    __shared__ __align__(16) float s_cost[256];
    __shared__ __align__(16) float s_part[512];

    const int b = blockIdx.x >> 3;
    const int rank = blockIdx.x & 7;
    const int t = threadIdx.x;
    const int jl = t >> 4, p = t & 15;
    const int j = rank * 32 + jl;          // candidate this thread serves in phase A
    const int h0 = p * 16;

    // vptr slice cached in regs (used every step); kproj NOT cached (i<=1 only)
    float4 vp[4];
#pragma unroll
    for (int g = 0; g < 4; g++) vp[g] = *(const float4*)(vptr + h0 + 4 * g);

    if (t < 256) s_qbase[t] = g_base[b * 256 + t] + g_ivq[t];
    if (rank == 0) {
        for (int q = t; q < 1024; q += 512) s_node[q] = node[(size_t)b * 1024 + q];
        if (t < 256) s_cost[t] = costs[(size_t)b * 256 + t];
    }
    if (t < 16) s_slots[t >> 3][t & 7][3] = 0.0f;   // zero tags, both buffers
    __syncthreads();
    CLUSTER_SYNC();                       // peers resident + init visible

    // producer remote addresses for lanes 0..7 of warp 0 (both buffers)
    uint32_t rem0 = 0, rem1 = 0;
    if (t < 8) {
        rem0 = mapa_rank(smem_u32(&s_slots[0][rank][0]), (uint32_t)t);
        rem1 = mapa_rank(smem_u32(&s_slots[1][rank][0]), (uint32_t)t);
    }

    float lp = 0.0f, rw = 0.0f;           // rank0 t0 only
    int st_i = 0;
    int cur = 0;                          // prev chosen idx
    int masked = 0;                       // warp0 lane t: candidate rank*32+t masked?
    int amask = 0;                        // phase-A: candidate j masked? (warp-uniform)
    float4 qk[4];

    for (int i = 0; i < MMAX; i++) {
        // gumbel prefetch for phase-B warp
        float gv = 0.0f;
        if (t < 32) gv = g_gumbel[((size_t)b * MMAX + i) * 256 + rank * 32 + t];

        // phase A (skipped wholesale once this thread's cell is masked; warp-uniform)
        if (!amask) {
            float4 gb[4];
            if (i == 0) {
#pragma unroll
                for (int g = 0; g < 4; g++) gb[g] = make_float4(0.f, 0.f, 0.f, 0.f);
            } else {
                const float* gr = g_Gbot + ((size_t)b * 256 + cur) * 256 + h0;
#pragma unroll
                for (int g = 0; g < 4; g++) gb[g] = *(const float4*)(gr + 4 * g);
            }
            if (i <= 1) {
                const float* kpr = g_kproj + ((size_t)b * 256 + j) * 256 + h0;
#pragma unroll
                for (int g = 0; g < 4; g++) {
                    float4 kv = *(const float4*)(kpr + 4 * g);
                    float4 qb = *(const float4*)(s_qbase + h0 + 4 * g);
                    qk[g] = make_float4(qb.x + kv.x, qb.y + kv.y,
                                        qb.z + kv.z, qb.w + kv.w);
                }
            }
            float acc = 0.0f;
#pragma unroll
            for (int g = 0; g < 4; g++) {
                acc = fmaf(tanh_fast(qk[g].x + gb[g].x), vp[g].x, acc);
                acc = fmaf(tanh_fast(qk[g].y + gb[g].y), vp[g].y, acc);
                acc = fmaf(tanh_fast(qk[g].z + gb[g].z), vp[g].z, acc);
                acc = fmaf(tanh_fast(qk[g].w + gb[g].w), vp[g].w, acc);
            }
            acc += __shfl_xor_sync(0xffffffffu, acc, 1);
            acc += __shfl_xor_sync(0xffffffffu, acc, 2);
            acc += __shfl_xor_sync(0xffffffffu, acc, 4);
            acc += __shfl_xor_sync(0xffffffffu, acc, 8);
            if (p == 0) s_u[jl] = acc;
        }
        __syncthreads();

        // phase B (warp 0): logits, fixed-shift expsum + gumbel argmax
        if (t < 32) {
            float lg = masked ? -1e9f : 10.0f * tanh_xla(s_u[t]);
            float ex = __expf(lg - 10.0f);                // fixed shift K=10
            float sc = lg + gv;
            int   si = t;
            float sl = lg;
#pragma unroll
            for (int o = 16; o; o >>= 1) {
                float ov = __shfl_xor_sync(0xffffffffu, sc, o);
                int   oi = __shfl_xor_sync(0xffffffffu, si, o);
                float ol = __shfl_xor_sync(0xffffffffu, sl, o);
                ex += __shfl_xor_sync(0xffffffffu, ex, o);
                if (ov > sc || (ov == sc && oi < si)) { sc = ov; si = oi; sl = ol; }
            }
            // lanes 0..7 fan out (payload, then release-tagged word) to all ranks
            if (t < 8) {
                uint32_t rem = (i & 1) ? rem1 : rem0;
                uint32_t tag = (uint32_t)(rank * 32 + si) | ((uint32_t)(i + 1) << 16);
                st_cluster_b64(rem + 0, pack2(sc, sl));
                st_cluster_rel_b64(rem + 8, pack2(ex, __uint_as_float(tag)));
            }
        }
        // spin: lanes 0..7 wait for their rank's tag in LOCAL smem
        if (t < 8) {
            uint32_t a = smem_u32(&s_slots[i & 1][t][3]);
            uint32_t want = (uint32_t)(i + 1) << 16;
            uint32_t v;
            do { v = ld_acq_shared_b32(a); } while ((v & 0xFFFF0000u) != want);
        }
        __syncthreads();   // all 8 slots visible to whole CTA

        // combine (redundant in all threads): winner across ranks
        const float (*sl8)[4] = s_slots[i & 1];
        float bsc = sl8[0][0];
        float bsl = sl8[0][1];
        float gsum = sl8[0][2];
        int gidx = __float_as_uint(sl8[0][3]) & 0xFFFF;
#pragma unroll
        for (int r = 1; r < 8; r++) {
            float scr = sl8[r][0];
            gsum += sl8[r][2];
            if (scr > bsc) {
                bsc = scr; bsl = sl8[r][1];
                gidx = __float_as_uint(sl8[r][3]) & 0xFFFF;
            }
        }
        cur = gidx;
        // mask whole 4-node cell of the winner
        amask |= ((gidx >> 2) == (j >> 2)) ? 1 : 0;                       // phase-A map
        if (t < 32) masked |= ((gidx >> 2) == ((rank * 32 + t) >> 2)) ? 1 : 0;  // phase-B map

        if (rank == 0 && t == 0) {
            lp += bsl - 10.0f - __logf(gsum);
            if (i > 0) {
                float dx = s_node[gidx * 4 + 0] - s_node[st_i * 4 + 2];
                float dy = s_node[gidx * 4 + 1] - s_node[st_i * 4 + 3];
                rw += sqrtf(dx * dx + dy * dy) + s_cost[st_i] + s_cost[gidx];
            }
            st_i = gidx;
            out[32 + b * MMAX + i] = (float)gidx;
        }

        if (i == 0) {
            // one-time: qbase = base + Gtop[init], Gtop row computed on the fly
            int init_i = gidx;
            int half = t >> 8, tt = t & 255;
            const float* erow = emb + ((size_t)b * 256 + init_i) * 256 + half * 128;
            const float* wrow = g_WvWq + (size_t)half * 128 * 256 + tt;
            float p0 = 0, p1 = 0, p2 = 0, p3 = 0;
            for (int k = 0; k < 128; k += 4) {
                p0 = fmaf(erow[k + 0], wrow[(k + 0) * 256], p0);
                p1 = fmaf(erow[k + 1], wrow[(k + 1) * 256], p1);
                p2 = fmaf(erow[k + 2], wrow[(k + 2) * 256], p2);
                p3 = fmaf(erow[k + 3], wrow[(k + 3) * 256], p3);
            }
            s_part[t] = (p0 + p1) + (p2 + p3);
            __syncthreads();
            if (t < 256)
                s_qbase[t] = g_base[b * 256 + t] + s_part[t] + s_part[t + 256];
            __syncthreads();
        }
    }
    if (rank == 0 && t == 0) { out[b] = lp; out[16 + b] = rw; }
    CLUSTER_SYNC();   // no CTA exits while peers may still receive its stores
}

extern "C" void kernel_launch(void* const* d_in, const int* in_sizes, int n_in,
                              void* d_out, int out_size) {
    const float* cell_embed = (const float*)d_in[0];
    const float* original_node = (const float*)d_in[1];
    // d_in[2] maze (unused), d_in[3] num_cell (=64)
    const float* costs  = (const float*)d_in[4];
    const float* init_w = (const float*)d_in[5];
    const float* Whc    = (const float*)d_in[6];
    const float* bhc    = (const float*)d_in[7];
    const float* Wv     = (const float*)d_in[8];
    const float* bv     = (const float*)d_in[9];
    const float* Wq     = (const float*)d_in[10];
    const float* Wk     = (const float*)d_in[11];
    const float* vptr   = (const float*)d_in[12];
    float* out = (float*)d_out;

    dummy_kernel<<<1, 32>>>();   // shifts ncu -s5 capture onto decode_kernel
    k1_kernel<<<1120, 256>>>(Wv, Wq, cell_embed);
    k2_kernel<<<529, 256>>>(cell_embed, Wk, init_w, Whc, bhc, bv, Wq);
    decode_kernel<<<128, 512>>>(original_node, costs, vptr, cell_embed, out);
}

// round 14
// speedup vs baseline: 1.0015x; 1.0015x over previous
#include <cuda_runtime.h>
#include <cstdint>
#include <cstddef>

#define Bb 16
#define MMAX 64

// ---------------- device scratch (allocation-free rule) ----------------
__device__ __align__(16) float g_WvWq[512 * 256];
__device__ __align__(16) float g_ivq[256];
__device__ __align__(16) float g_base[Bb * 256];
__device__ __align__(16) float g_hpart[Bb * 4 * 256];
__device__ __align__(16) float g_kproj[Bb * 256 * 256];
__device__ __align__(16) float g_Gbot[Bb * 256 * 256];
__device__ __align__(16) float g_gumbel[Bb * MMAX * 256];

// ---------------- XLA/Eigen rational tanh -------------------------------
__device__ __forceinline__ float tanh_xla(float x) {
    float xc = fminf(fmaxf(x, -9.0f), 9.0f);
    float s = xc * xc;
    float p = -2.76076847742355e-16f;
    p = fmaf(p, s, 2.00018790482477e-13f);
    p = fmaf(p, s, -8.60467152213735e-11f);
    p = fmaf(p, s, 5.12229709037114e-08f);
    p = fmaf(p, s, 1.48572235717979e-05f);
    p = fmaf(p, s, 6.37261928875436e-04f);
    p = fmaf(p, s, 4.89352455891786e-03f);
    p = p * xc;
    float q = 1.19825839466702e-06f;
    q = fmaf(q, s, 1.18534705686654e-04f);
    q = fmaf(q, s, 2.26843463243900e-03f);
    q = fmaf(q, s, 4.89352518554385e-03f);
    float r0;
    asm("rcp.approx.f32 %0, %1;" : "=f"(r0) : "f"(q));
    r0 = r0 * fmaf(-q, r0, 2.0f);            // Newton -> ~fp32 exact
    return p * r0;
}

// fast version (rcp.approx only, rel err ~1.6e-7) for the phase-A dot
__device__ __forceinline__ float tanh_fast(float x) {
    float xc = fminf(fmaxf(x, -9.0f), 9.0f);
    float s = xc * xc;
    float p = -2.76076847742355e-16f;
    p = fmaf(p, s, 2.00018790482477e-13f);
    p = fmaf(p, s, -8.60467152213735e-11f);
    p = fmaf(p, s, 5.12229709037114e-08f);
    p = fmaf(p, s, 1.48572235717979e-05f);
    p = fmaf(p, s, 6.37261928875436e-04f);
    p = fmaf(p, s, 4.89352455891786e-03f);
    p = p * xc;
    float q = 1.19825839466702e-06f;
    q = fmaf(q, s, 1.18534705686654e-04f);
    q = fmaf(q, s, 2.26843463243900e-03f);
    q = fmaf(q, s, 4.89352518554385e-03f);
    float r0;
    asm("rcp.approx.f32 %0, %1;" : "=f"(r0) : "f"(q));
    return p * r0;
}

// ---------------- threefry2x32 (JAX schedule) ---------------------------
__device__ __forceinline__ uint32_t rotl32(uint32_t v, int d) {
    return (v << d) | (v >> (32 - d));
}
__device__ __forceinline__ void threefry2x32(uint32_t k0, uint32_t k1,
                                             uint32_t x0, uint32_t x1,
                                             uint32_t& o0, uint32_t& o1) {
    uint32_t k2 = k0 ^ k1 ^ 0x1BD11BDAu;
    x0 += k0; x1 += k1;
#define TFR(r) { x0 += x1; x1 = rotl32(x1, r); x1 ^= x0; }
    TFR(13) TFR(15) TFR(26) TFR(6)   x0 += k1; x1 += k2 + 1u;
    TFR(17) TFR(29) TFR(16) TFR(24)  x0 += k2; x1 += k0 + 2u;
    TFR(13) TFR(15) TFR(26) TFR(6)   x0 += k0; x1 += k1 + 3u;
    TFR(17) TFR(29) TFR(16) TFR(24)  x0 += k1; x1 += k2 + 4u;
    TFR(13) TFR(15) TFR(26) TFR(6)   x0 += k2; x1 += k0 + 5u;
#undef TFR
    o0 = x0; o1 = x1;
}

// ---------------- cluster / DSMEM helpers -------------------------------
#define CLUSTER_SYNC() do { \
    asm volatile("barrier.cluster.arrive.aligned;" ::: "memory"); \
    asm volatile("barrier.cluster.wait.aligned;"   ::: "memory"); } while (0)

__device__ __forceinline__ uint32_t smem_u32(const void* p) {
    return (uint32_t)__cvta_generic_to_shared(p);
}
__device__ __forceinline__ uint32_t mapa_rank(uint32_t saddr, uint32_t r) {
    uint32_t o;
    asm("mapa.shared::cluster.u32 %0, %1, %2;" : "=r"(o) : "r"(saddr), "r"(r));
    return o;
}
__device__ __forceinline__ void st_cluster_b64(uint32_t addr, uint64_t v) {
    asm volatile("st.shared::cluster.b64 [%0], %1;" :: "r"(addr), "l"(v));
}
__device__ __forceinline__ void st_cluster_rel_b64(uint32_t addr, uint64_t v) {
    asm volatile("st.release.cluster.shared::cluster.b64 [%0], %1;"
                 :: "r"(addr), "l"(v) : "memory");
}
__device__ __forceinline__ uint32_t ld_acq_shared_b32(uint32_t addr) {
    uint32_t v;
    asm volatile("ld.acquire.cluster.shared::cta.b32 %0, [%1];"
                 : "=r"(v) : "r"(addr) : "memory");
    return v;
}
__device__ __forceinline__ uint64_t pack2(float a, float b) {
    return (uint64_t)__float_as_uint(a) | ((uint64_t)__float_as_uint(b) << 32);
}

// ---------------- profile-alignment dummy (shifts ncu -s5 onto decode) --
__global__ void dummy_kernel() {}

// ---------------- 64x64 tiled GEMM (BK=16, 256 thr, 4x4 micro) ----------
__device__ __forceinline__ void gemm64(const float* __restrict__ A,
                                       const float* __restrict__ B,
                                       float* __restrict__ C,
                                       int K, int N, int bx, int by) {
    __shared__ __align__(16) float As[16][68];
    __shared__ __align__(16) float Bs[16][68];
    int t = threadIdx.x;
    int tx = t & 15, ty = t >> 4;
    int row0 = by * 64, col0 = bx * 64;
    int am = t >> 2, akc = (t & 3) * 4;
    int bk = t >> 4, bnc = (t & 15) * 4;
    float acc[4][4];
#pragma unroll
    for (int u = 0; u < 4; u++)
#pragma unroll
        for (int v = 0; v < 4; v++) acc[u][v] = 0.0f;

    for (int k0 = 0; k0 < K; k0 += 16) {
        float4 av = *(const float4*)(A + (size_t)(row0 + am) * K + k0 + akc);
        As[akc + 0][am] = av.x; As[akc + 1][am] = av.y;
        As[akc + 2][am] = av.z; As[akc + 3][am] = av.w;
        *(float4*)&Bs[bk][bnc] =
            *(const float4*)(B + (size_t)(k0 + bk) * N + col0 + bnc);
        __syncthreads();
#pragma unroll
        for (int kk = 0; kk < 16; kk++) {
            float4 a  = *(const float4*)&As[kk][ty * 4];
            float4 bb = *(const float4*)&Bs[kk][tx * 4];
            acc[0][0] = fmaf(a.x, bb.x, acc[0][0]);
            acc[0][1] = fmaf(a.x, bb.y, acc[0][1]);
            acc[0][2] = fmaf(a.x, bb.z, acc[0][2]);
            acc[0][3] = fmaf(a.x, bb.w, acc[0][3]);
            acc[1][0] = fmaf(a.y, bb.x, acc[1][0]);
            acc[1][1] = fmaf(a.y, bb.y, acc[1][1]);
            acc[1][2] = fmaf(a.y, bb.z, acc[1][2]);
            acc[1][3] = fmaf(a.y, bb.w, acc[1][3]);
            acc[2][0] = fmaf(a.z, bb.x, acc[2][0]);
            acc[2][1] = fmaf(a.z, bb.y, acc[2][1]);
            acc[2][2] = fmaf(a.z, bb.z, acc[2][2]);
            acc[2][3] = fmaf(a.z, bb.w, acc[2][3]);
            acc[3][0] = fmaf(a.w, bb.x, acc[3][0]);
            acc[3][1] = fmaf(a.w, bb.y, acc[3][1]);
            acc[3][2] = fmaf(a.w, bb.z, acc[3][2]);
            acc[3][3] = fmaf(a.w, bb.w, acc[3][3]);
        }
        __syncthreads();
    }
#pragma unroll
    for (int u = 0; u < 4; u++) {
        float4 o = make_float4(acc[u][0], acc[u][1], acc[u][2], acc[u][3]);
        *(float4*)(C + (size_t)(row0 + ty * 4 + u) * N + col0 + tx * 4) = o;
    }
}

// ---------------- K1: WvWq tiles + mean-partials + gumbel (flat) --------
__global__ void k1_kernel(const float* __restrict__ Wv,
                          const float* __restrict__ Wq,
                          const float* __restrict__ emb) {
    int bid = blockIdx.x;
    if (bid < 32) {
        gemm64(Wv, Wq, g_WvWq, 256, 256, bid & 3, bid >> 2);
    } else if (bid < 96) {
        int id = bid - 32, b = id >> 2, qq = id & 3;
        const float* E = emb + ((size_t)b * 256 + qq * 64) * 256;
        int e = threadIdx.x;
        float a0 = 0, a1 = 0, a2 = 0, a3 = 0;
        for (int r = 0; r < 64; r += 4) {
            a0 += E[(size_t)(r + 0) * 256 + e];
            a1 += E[(size_t)(r + 1) * 256 + e];
            a2 += E[(size_t)(r + 2) * 256 + e];
            a3 += E[(size_t)(r + 3) * 256 + e];
        }
        g_hpart[((b * 4 + qq) << 8) + e] = (a0 + a1) + (a2 + a3);
    } else {
        int pair = bid - 96;                 // 0..1023
        int b = pair >> 6, i = pair & 63;
        int j = threadIdx.x;
        uint32_t b0, b1, s0, s1, o0, o1;
        threefry2x32(0u, 42u, 0u, (uint32_t)b, b0, b1);
        threefry2x32(b0, b1, 0u, (uint32_t)i, s0, s1);
        threefry2x32(s0, s1, 0u, (uint32_t)j, o0, o1);
        uint32_t bits = o0 ^ o1;
        float f = __uint_as_float((bits >> 9) | 0x3F800000u) - 1.0f;
        float u = fmaxf(1.17549435e-38f, f);
        g_gumbel[((size_t)b * MMAX + i) * 256 + j] = -logf(-logf(u));
    }
}

// ---------------- K2: kproj+Gbot GEMMs + ivq + base finalize ------------
__global__ void k2_kernel(const float* __restrict__ emb,
                          const float* __restrict__ Wk,
                          const float* __restrict__ init_w,
                          const float* __restrict__ Whc,
                          const float* __restrict__ bhc,
                          const float* __restrict__ bv,
                          const float* __restrict__ Wq) {
    int bid = blockIdx.x;
    if (bid < 512) {
        int item = bid >> 5;
        int r = bid & 31, mat = r >> 4, tile = r & 15;
        const float* A = emb + (size_t)item * 65536;
        const float* B = mat ? (g_WvWq + 65536) : Wk;   // Gbot uses Wv bottom half
        float* C = (mat ? g_Gbot : g_kproj) + (size_t)item * 65536;
        gemm64(A, B, C, 256, 256, tile & 3, tile >> 2);
    } else if (bid == 512) {
        int h = threadIdx.x;
        float a = 0.0f;
        for (int k = 0; k < 512; k++) a = fmaf(init_w[k], g_WvWq[k * 256 + h], a);
        g_ivq[h] = a;
    } else {
        int b = bid - 513;
        __shared__ __align__(16) float sh[256];
        __shared__ __align__(16) float st1[256];
        int e = threadIdx.x;
        float hb = (g_hpart[(b * 4 + 0) * 256 + e] + g_hpart[(b * 4 + 1) * 256 + e]
                  + g_hpart[(b * 4 + 2) * 256 + e] + g_hpart[(b * 4 + 3) * 256 + e])
                  * (1.0f / 256.0f);
        sh[e] = hb;
        __syncthreads();
        float a = 0.0f;
        for (int k = 0; k < 256; k++) a = fmaf(sh[k], Whc[k * 256 + e], a);
        st1[e] = a + bhc[e] + bv[e];
        __syncthreads();
        float a2 = 0.0f;
        for (int k = 0; k < 256; k++) a2 = fmaf(st1[k], Wq[k * 256 + e], a2);
        g_base[b * 256 + e] = a2;
    }
}

// ---------------- decode: 8-CTA cluster, tagged DSMEM exchange ----------
// slot layout per rank: [sc, sl, ex, tagword]; tagword = gidx | (step+1)<<16
__global__ void __cluster_dims__(8, 1, 1) __launch_bounds__(512, 1)
decode_kernel(const float* __restrict__ node, const float* __restrict__ costs,
              const float* __restrict__ vptr, const float* __restrict__ emb,
              float* __restrict__ out) {
    __shared__ __align__(16) float s_qbase[256];
    __shared__ __align__(16) float s_u[32];
    __shared__ __align__(16) float s_slots[2][8][4];   // [buf][rank][sc,sl,ex,tag]
    __shared__ __align__(16) float s_node[1024];
    __shared__ __align__(16) float s_cost[256];
    __shared__ __align__(16) float s_part[512];

    const int b = blockIdx.x >> 3;
    const int rank = blockIdx.x & 7;
    const int t = threadIdx.x;
    const int jl = t >> 4, p = t & 15;
    const int j = rank * 32 + jl;          // candidate this thread serves in phase A
    const int h0 = p * 16;

    // vptr slice cached in regs (used every step); kproj NOT cached (i<=1 only)
    float4 vp[4];
#pragma unroll
    for (int g = 0; g < 4; g++) vp[g] = *(const float4*)(vptr + h0 + 4 * g);

    if (t < 256) s_qbase[t] = g_base[b * 256 + t] + g_ivq[t];
    if (rank == 0) {
        for (int q = t; q < 1024; q += 512) s_node[q] = node[(size_t)b * 1024 + q];
        if (t < 256) s_cost[t] = costs[(size_t)b * 256 + t];
    }
    if (t < 16) s_slots[t >> 3][t & 7][3] = 0.0f;   // zero tags, both buffers
    __syncthreads();
    CLUSTER_SYNC();                       // peers resident + init visible

    // producer remote addresses for lanes 0..7 of warp 0 (both buffers)
    uint32_t rem0 = 0, rem1 = 0;
    if (t < 8) {
        rem0 = mapa_rank(smem_u32(&s_slots[0][rank][0]), (uint32_t)t);
        rem1 = mapa_rank(smem_u32(&s_slots[1][rank][0]), (uint32_t)t);
    }

    float lp = 0.0f, rw = 0.0f;           // rank0 t0 only
    int st_i = 0;
    int cur = 0;                          // prev chosen idx
    int masked = 0;                       // warp0 lane t: candidate rank*32+t masked?
    int amask = 0;                        // phase-A: candidate j masked? (warp-uniform)
    float4 qk[4];

    for (int i = 0; i < MMAX; i++) {
        // gumbel prefetch for phase-B warp
        float gv = 0.0f;
        if (t < 32) gv = g_gumbel[((size_t)b * MMAX + i) * 256 + rank * 32 + t];

        // phase A (skipped wholesale once this thread's cell is masked; warp-uniform)
        if (!amask) {
            float4 gb[4];
            if (i == 0) {
#pragma unroll
                for (int g = 0; g < 4; g++) gb[g] = make_float4(0.f, 0.f, 0.f, 0.f);
            } else {
                const float* gr = g_Gbot + ((size_t)b * 256 + cur) * 256 + h0;
#pragma unroll
                for (int g = 0; g < 4; g++) gb[g] = *(const float4*)(gr + 4 * g);
            }
            if (i <= 1) {
                const float* kpr = g_kproj + ((size_t)b * 256 + j) * 256 + h0;
#pragma unroll
                for (int g = 0; g < 4; g++) {
                    float4 kv = *(const float4*)(kpr + 4 * g);
                    float4 qb = *(const float4*)(s_qbase + h0 + 4 * g);
                    qk[g] = make_float4(qb.x + kv.x, qb.y + kv.y,
                                        qb.z + kv.z, qb.w + kv.w);
                }
            }
            float acc = 0.0f;
#pragma unroll
            for (int g = 0; g < 4; g++) {
                acc = fmaf(tanh_fast(qk[g].x + gb[g].x), vp[g].x, acc);
                acc = fmaf(tanh_fast(qk[g].y + gb[g].y), vp[g].y, acc);
                acc = fmaf(tanh_fast(qk[g].z + gb[g].z), vp[g].z, acc);
                acc = fmaf(tanh_fast(qk[g].w + gb[g].w), vp[g].w, acc);
            }
            acc += __shfl_xor_sync(0xffffffffu, acc, 1);
            acc += __shfl_xor_sync(0xffffffffu, acc, 2);
            acc += __shfl_xor_sync(0xffffffffu, acc, 4);
            acc += __shfl_xor_sync(0xffffffffu, acc, 8);
            if (p == 0) s_u[jl] = acc;
        }
        __syncthreads();

        // phase B (warp 0): logits, fixed-shift expsum + gumbel argmax
        if (t < 32) {
            float lg = masked ? -1e9f : 10.0f * tanh_xla(s_u[t]);
            float ex = __expf(lg - 10.0f);                // fixed shift K=10
            float sc = lg + gv;
            int   si = t;
            float sl = lg;
#pragma unroll
            for (int o = 16; o; o >>= 1) {
                float ov = __shfl_xor_sync(0xffffffffu, sc, o);
                int   oi = __shfl_xor_sync(0xffffffffu, si, o);
                float ol = __shfl_xor_sync(0xffffffffu, sl, o);
                ex += __shfl_xor_sync(0xffffffffu, ex, o);
                if (ov > sc || (ov == sc && oi < si)) { sc = ov; si = oi; sl = ol; }
            }
            // lanes 0..7 fan out (payload, then release-tagged word) to all ranks
            if (t < 8) {
                uint32_t rem = (i & 1) ? rem1 : rem0;
                uint32_t tag = (uint32_t)(rank * 32 + si) | ((uint32_t)(i + 1) << 16);
                st_cluster_b64(rem + 0, pack2(sc, sl));
                st_cluster_rel_b64(rem + 8, pack2(ex, __uint_as_float(tag)));
            }
        }
        // spin: lanes 0..7 wait for their rank's tag in LOCAL smem
        if (t < 8) {
            uint32_t a = smem_u32(&s_slots[i & 1][t][3]);
            uint32_t want = (uint32_t)(i + 1) << 16;
            uint32_t v;
            do { v = ld_acq_shared_b32(a); } while ((v & 0xFFFF0000u) != want);
        }
        __syncthreads();   // all 8 slots visible to whole CTA

        // combine (redundant in all threads): winner across ranks
        const float (*sl8)[4] = s_slots[i & 1];
        float bsc = sl8[0][0];
        float bsl = sl8[0][1];
        float gsum = sl8[0][2];
        int gidx = __float_as_uint(sl8[0][3]) & 0xFFFF;
#pragma unroll
        for (int r = 1; r < 8; r++) {
            float scr = sl8[r][0];
            gsum += sl8[r][2];
            if (scr > bsc) {
                bsc = scr; bsl = sl8[r][1];
                gidx = __float_as_uint(sl8[r][3]) & 0xFFFF;
            }
        }
        cur = gidx;
        // mask whole 4-node cell of the winner
        amask |= ((gidx >> 2) == (j >> 2)) ? 1 : 0;                       // phase-A map
        if (t < 32) masked |= ((gidx >> 2) == ((rank * 32 + t) >> 2)) ? 1 : 0;  // phase-B map

        if (rank == 0 && t == 0) {
            lp += bsl - 10.0f - __logf(gsum);
            if (i > 0) {
                float dx = s_node[gidx * 4 + 0] - s_node[st_i * 4 + 2];
                float dy = s_node[gidx * 4 + 1] - s_node[st_i * 4 + 3];
                rw += sqrtf(dx * dx + dy * dy) + s_cost[st_i] + s_cost[gidx];
            }
            st_i = gidx;
            out[32 + b * MMAX + i] = (float)gidx;
        }

        if (i == 0) {
            // one-time: qbase = base + Gtop[init], Gtop row computed on the fly
            int init_i = gidx;
            int half = t >> 8, tt = t & 255;
            const float* erow = emb + ((size_t)b * 256 + init_i) * 256 + half * 128;
            const float* wrow = g_WvWq + (size_t)half * 128 * 256 + tt;
            float p0 = 0, p1 = 0, p2 = 0, p3 = 0;
            for (int k = 0; k < 128; k += 4) {
                p0 = fmaf(erow[k + 0], wrow[(k + 0) * 256], p0);
                p1 = fmaf(erow[k + 1], wrow[(k + 1) * 256], p1);
                p2 = fmaf(erow[k + 2], wrow[(k + 2) * 256], p2);
                p3 = fmaf(erow[k + 3], wrow[(k + 3) * 256], p3);
            }
            s_part[t] = (p0 + p1) + (p2 + p3);
            __syncthreads();
            if (t < 256)
                s_qbase[t] = g_base[b * 256 + t] + s_part[t] + s_part[t + 256];
            __syncthreads();
        }
    }
    if (rank == 0 && t == 0) { out[b] = lp; out[16 + b] = rw; }
    CLUSTER_SYNC();   // no CTA exits while peers may still receive its stores
}

extern "C" void kernel_launch(void* const* d_in, const int* in_sizes, int n_in,
                              void* d_out, int out_size) {
    const float* cell_embed = (const float*)d_in[0];
    const float* original_node = (const float*)d_in[1];
    // d_in[2] maze (unused), d_in[3] num_cell (=64)
    const float* costs  = (const float*)d_in[4];
    const float* init_w = (const float*)d_in[5];
    const float* Whc    = (const float*)d_in[6];
    const float* bhc    = (const float*)d_in[7];
    const float* Wv     = (const float*)d_in[8];
    const float* bv     = (const float*)d_in[9];
    const float* Wq     = (const float*)d_in[10];
    const float* Wk     = (const float*)d_in[11];
    const float* vptr   = (const float*)d_in[12];
    float* out = (float*)d_out;

    dummy_kernel<<<1, 32>>>();   // shifts ncu -s5 capture onto decode_kernel
    k1_kernel<<<1120, 256>>>(Wv, Wq, cell_embed);
    k2_kernel<<<529, 256>>>(cell_embed, Wk, init_w, Whc, bhc, bv, Wq);
    decode_kernel<<<128, 512>>>(original_node, costs, vptr, cell_embed, out);
}

// round 15
// speedup vs baseline: 1.1035x; 1.1019x over previous
#include <cuda_runtime.h>
#include <cstdint>
#include <cstddef>

#define Bb 16
#define MMAX 64

// ---------------- device scratch (allocation-free rule) ----------------
__device__ __align__(16) float g_WvWq[512 * 256];
__device__ __align__(16) float g_ivq[256];
__device__ __align__(16) float g_base[Bb * 256];
__device__ __align__(16) float g_hpart[Bb * 4 * 256];
__device__ __align__(16) float g_kproj[Bb * 256 * 256];
__device__ __align__(16) float g_Gbot[Bb * 256 * 256];
__device__ __align__(16) float g_gumbel[Bb * MMAX * 256];

// ---------------- XLA/Eigen rational tanh (rcp.approx form) -------------
__device__ __forceinline__ float tanh_fast(float x) {
    float xc = fminf(fmaxf(x, -9.0f), 9.0f);
    float s = xc * xc;
    float p = -2.76076847742355e-16f;
    p = fmaf(p, s, 2.00018790482477e-13f);
    p = fmaf(p, s, -8.60467152213735e-11f);
    p = fmaf(p, s, 5.12229709037114e-08f);
    p = fmaf(p, s, 1.48572235717979e-05f);
    p = fmaf(p, s, 6.37261928875436e-04f);
    p = fmaf(p, s, 4.89352455891786e-03f);
    p = p * xc;
    float q = 1.19825839466702e-06f;
    q = fmaf(q, s, 1.18534705686654e-04f);
    q = fmaf(q, s, 2.26843463243900e-03f);
    q = fmaf(q, s, 4.89352518554385e-03f);
    float r0;
    asm("rcp.approx.f32 %0, %1;" : "=f"(r0) : "f"(q));
    return p * r0;
}

// ---------------- threefry2x32 (JAX schedule) ---------------------------
__device__ __forceinline__ uint32_t rotl32(uint32_t v, int d) {
    return (v << d) | (v >> (32 - d));
}
__device__ __forceinline__ void threefry2x32(uint32_t k0, uint32_t k1,
                                             uint32_t x0, uint32_t x1,
                                             uint32_t& o0, uint32_t& o1) {
    uint32_t k2 = k0 ^ k1 ^ 0x1BD11BDAu;
    x0 += k0; x1 += k1;
#define TFR(r) { x0 += x1; x1 = rotl32(x1, r); x1 ^= x0; }
    TFR(13) TFR(15) TFR(26) TFR(6)   x0 += k1; x1 += k2 + 1u;
    TFR(17) TFR(29) TFR(16) TFR(24)  x0 += k2; x1 += k0 + 2u;
    TFR(13) TFR(15) TFR(26) TFR(6)   x0 += k0; x1 += k1 + 3u;
    TFR(17) TFR(29) TFR(16) TFR(24)  x0 += k1; x1 += k2 + 4u;
    TFR(13) TFR(15) TFR(26) TFR(6)   x0 += k2; x1 += k0 + 5u;
#undef TFR
    o0 = x0; o1 = x1;
}

// ---------------- cluster / DSMEM helpers -------------------------------
#define CLUSTER_SYNC() do { \
    asm volatile("barrier.cluster.arrive.aligned;" ::: "memory"); \
    asm volatile("barrier.cluster.wait.aligned;"   ::: "memory"); } while (0)

__device__ __forceinline__ uint32_t smem_u32(const void* p) {
    return (uint32_t)__cvta_generic_to_shared(p);
}
__device__ __forceinline__ uint32_t mapa_rank(uint32_t saddr, uint32_t r) {
    uint32_t o;
    asm("mapa.shared::cluster.u32 %0, %1, %2;" : "=r"(o) : "r"(saddr), "r"(r));
    return o;
}
__device__ __forceinline__ void st_cluster_b64(uint32_t addr, uint64_t v) {
    asm volatile("st.shared::cluster.b64 [%0], %1;" :: "r"(addr), "l"(v));
}
__device__ __forceinline__ uint64_t pack2(float a, float b) {
    return (uint64_t)__float_as_uint(a) | ((uint64_t)__float_as_uint(b) << 32);
}

// ---------------- profile-alignment dummy (shifts ncu -s5 onto decode) --
__global__ void dummy_kernel() {}

// ---------------- 64x64 tiled GEMM (BK=16, 256 thr, 4x4 micro) ----------
__device__ __forceinline__ void gemm64(const float* __restrict__ A,
                                       const float* __restrict__ B,
                                       float* __restrict__ C,
                                       int K, int N, int bx, int by) {
    __shared__ __align__(16) float As[16][68];
    __shared__ __align__(16) float Bs[16][68];
    int t = threadIdx.x;
    int tx = t & 15, ty = t >> 4;
    int row0 = by * 64, col0 = bx * 64;
    int am = t >> 2, akc = (t & 3) * 4;
    int bk = t >> 4, bnc = (t & 15) * 4;
    float acc[4][4];
#pragma unroll
    for (int u = 0; u < 4; u++)
#pragma unroll
        for (int v = 0; v < 4; v++) acc[u][v] = 0.0f;

    for (int k0 = 0; k0 < K; k0 += 16) {
        float4 av = *(const float4*)(A + (size_t)(row0 + am) * K + k0 + akc);
        As[akc + 0][am] = av.x; As[akc + 1][am] = av.y;
        As[akc + 2][am] = av.z; As[akc + 3][am] = av.w;
        *(float4*)&Bs[bk][bnc] =
            *(const float4*)(B + (size_t)(k0 + bk) * N + col0 + bnc);
        __syncthreads();
#pragma unroll
        for (int kk = 0; kk < 16; kk++) {
            float4 a  = *(const float4*)&As[kk][ty * 4];
            float4 bb = *(const float4*)&Bs[kk][tx * 4];
            acc[0][0] = fmaf(a.x, bb.x, acc[0][0]);
            acc[0][1] = fmaf(a.x, bb.y, acc[0][1]);
            acc[0][2] = fmaf(a.x, bb.z, acc[0][2]);
            acc[0][3] = fmaf(a.x, bb.w, acc[0][3]);
            acc[1][0] = fmaf(a.y, bb.x, acc[1][0]);
            acc[1][1] = fmaf(a.y, bb.y, acc[1][1]);
            acc[1][2] = fmaf(a.y, bb.z, acc[1][2]);
            acc[1][3] = fmaf(a.y, bb.w, acc[1][3]);
            acc[2][0] = fmaf(a.z, bb.x, acc[2][0]);
            acc[2][1] = fmaf(a.z, bb.y, acc[2][1]);
            acc[2][2] = fmaf(a.z, bb.z, acc[2][2]);
            acc[2][3] = fmaf(a.z, bb.w, acc[2][3]);
            acc[3][0] = fmaf(a.w, bb.x, acc[3][0]);
            acc[3][1] = fmaf(a.w, bb.y, acc[3][1]);
            acc[3][2] = fmaf(a.w, bb.z, acc[3][2]);
            acc[3][3] = fmaf(a.w, bb.w, acc[3][3]);
        }
        __syncthreads();
    }
#pragma unroll
    for (int u = 0; u < 4; u++) {
        float4 o = make_float4(acc[u][0], acc[u][1], acc[u][2], acc[u][3]);
        *(float4*)(C + (size_t)(row0 + ty * 4 + u) * N + col0 + tx * 4) = o;
    }
}

// ---------------- K1: WvWq tiles + mean-partials + gumbel (flat) --------
__global__ void k1_kernel(const float* __restrict__ Wv,
                          const float* __restrict__ Wq,
                          const float* __restrict__ emb) {
    int bid = blockIdx.x;
    if (bid < 32) {
        gemm64(Wv, Wq, g_WvWq, 256, 256, bid & 3, bid >> 2);
    } else if (bid < 96) {
        int id = bid - 32, b = id >> 2, qq = id & 3;
        const float* E = emb + ((size_t)b * 256 + qq * 64) * 256;
        int e = threadIdx.x;
        float a0 = 0, a1 = 0, a2 = 0, a3 = 0;
        for (int r = 0; r < 64; r += 4) {
            a0 += E[(size_t)(r + 0) * 256 + e];
            a1 += E[(size_t)(r + 1) * 256 + e];
            a2 += E[(size_t)(r + 2) * 256 + e];
            a3 += E[(size_t)(r + 3) * 256 + e];
        }
        g_hpart[((b * 4 + qq) << 8) + e] = (a0 + a1) + (a2 + a3);
    } else {
        int pair = bid - 96;                 // 0..1023
        int b = pair >> 6, i = pair & 63;
        int j = threadIdx.x;
        uint32_t b0, b1, s0, s1, o0, o1;
        threefry2x32(0u, 42u, 0u, (uint32_t)b, b0, b1);
        threefry2x32(b0, b1, 0u, (uint32_t)i, s0, s1);
        threefry2x32(s0, s1, 0u, (uint32_t)j, o0, o1);
        uint32_t bits = o0 ^ o1;
        float f = __uint_as_float((bits >> 9) | 0x3F800000u) - 1.0f;
        float u = fmaxf(1.17549435e-38f, f);
        g_gumbel[((size_t)b * MMAX + i) * 256 + j] = -logf(-logf(u));
    }
}

// ---------------- K2: kproj+Gbot GEMMs + ivq + base finalize ------------
__global__ void k2_kernel(const float* __restrict__ emb,
                          const float* __restrict__ Wk,
                          const float* __restrict__ init_w,
                          const float* __restrict__ Whc,
                          const float* __restrict__ bhc,
                          const float* __restrict__ bv,
                          const float* __restrict__ Wq) {
    int bid = blockIdx.x;
    if (bid < 512) {
        int item = bid >> 5;
        int r = bid & 31, mat = r >> 4, tile = r & 15;
        const float* A = emb + (size_t)item * 65536;
        const float* B = mat ? (g_WvWq + 65536) : Wk;   // Gbot uses Wv bottom half
        float* C = (mat ? g_Gbot : g_kproj) + (size_t)item * 65536;
        gemm64(A, B, C, 256, 256, tile & 3, tile >> 2);
    } else if (bid == 512) {
        int h = threadIdx.x;
        float a = 0.0f;
        for (int k = 0; k < 512; k++) a = fmaf(init_w[k], g_WvWq[k * 256 + h], a);
        g_ivq[h] = a;
    } else {
        int b = bid - 513;
        __shared__ __align__(16) float sh[256];
        __shared__ __align__(16) float st1[256];
        int e = threadIdx.x;
        float hb = (g_hpart[(b * 4 + 0) * 256 + e] + g_hpart[(b * 4 + 1) * 256 + e]
                  + g_hpart[(b * 4 + 2) * 256 + e] + g_hpart[(b * 4 + 3) * 256 + e])
                  * (1.0f / 256.0f);
        sh[e] = hb;
        __syncthreads();
        float a = 0.0f;
        for (int k = 0; k < 256; k++) a = fmaf(sh[k], Whc[k * 256 + e], a);
        st1[e] = a + bhc[e] + bv[e];
        __syncthreads();
        float a2 = 0.0f;
        for (int k = 0; k < 256; k++) a2 = fmaf(st1[k], Wq[k * 256 + e], a2);
        g_base[b * 256 + e] = a2;
    }
}

// ---------------- decode: 8-CTA cluster, deferred epilogue --------------
__global__ void __cluster_dims__(8, 1, 1) __launch_bounds__(512, 1)
decode_kernel(const float* __restrict__ node, const float* __restrict__ costs,
              const float* __restrict__ vptr, const float* __restrict__ emb,
              float* __restrict__ out) {
    __shared__ __align__(16) float s_qbase[256];
    __shared__ __align__(16) float s_u[32];
    __shared__ __align__(16) float s_slots[2][8][4];   // [buf][rank][sc,si,sl,ex]
    __shared__ __align__(16) float s_node[1024];
    __shared__ __align__(16) float s_cost[256];
    __shared__ __align__(16) float s_part[512];
    __shared__ __align__(16) float s_bsl[MMAX];        // rank0: saved winner lg
    __shared__ __align__(16) float s_gsum[MMAX];       // rank0: saved expsum
    __shared__ __align__(16) int   s_act[MMAX];        // rank0: saved actions
    __shared__ __align__(16) float s_red[128];

    const int b = blockIdx.x >> 3;
    const int rank = blockIdx.x & 7;
    const int t = threadIdx.x;
    const int jl = t >> 4, p = t & 15;
    const int j = rank * 32 + jl;          // candidate this thread serves in phase A
    const int h0 = p * 16;

    // per-thread constants: kproj row slice + vptr slice
    const float* kpr = g_kproj + ((size_t)b * 256 + j) * 256 + h0;
    float4 kp[4], vp[4];
#pragma unroll
    for (int g = 0; g < 4; g++) {
        kp[g] = *(const float4*)(kpr + 4 * g);
        vp[g] = *(const float4*)(vptr + h0 + 4 * g);
    }

    if (t < 256) s_qbase[t] = g_base[b * 256 + t] + g_ivq[t];
    if (rank == 0) {
        for (int q = t; q < 1024; q += 512) s_node[q] = node[(size_t)b * 1024 + q];
        if (t < 256) s_cost[t] = costs[(size_t)b * 256 + t];
    }
    __syncthreads();
    CLUSTER_SYNC();                       // peers resident + init visible

    const uint32_t slot_base0 = smem_u32(&s_slots[0][rank][0]);
    const uint32_t slot_base1 = smem_u32(&s_slots[1][rank][0]);

    int cur = 0;                          // prev chosen idx
    int masked = 0;                       // warp0 lane t: candidate rank*32+t masked?
    int amask = 0;                        // phase-A: candidate j masked? (warp-uniform)
    float4 qk[4];

    for (int i = 0; i < MMAX; i++) {
        // gumbel prefetch for phase-B warp
        float gv = 0.0f;
        if (t < 32) gv = g_gumbel[((size_t)b * MMAX + i) * 256 + rank * 32 + t];

        // phase A (skipped wholesale once this thread's cell is masked; warp-uniform)
        if (!amask) {
            float4 gb[4];
            if (i == 0) {
#pragma unroll
                for (int g = 0; g < 4; g++) gb[g] = make_float4(0.f, 0.f, 0.f, 0.f);
            } else {
                const float* gr = g_Gbot + ((size_t)b * 256 + cur) * 256 + h0;
#pragma unroll
                for (int g = 0; g < 4; g++) gb[g] = *(const float4*)(gr + 4 * g);
            }
            if (i <= 1) {
#pragma unroll
                for (int g = 0; g < 4; g++) {
                    float4 qb = *(const float4*)(s_qbase + h0 + 4 * g);
                    qk[g] = make_float4(qb.x + kp[g].x, qb.y + kp[g].y,
                                        qb.z + kp[g].z, qb.w + kp[g].w);
                }
            }
            float acc = 0.0f;
#pragma unroll
            for (int g = 0; g < 4; g++) {
                acc = fmaf(tanh_fast(qk[g].x + gb[g].x), vp[g].x, acc);
                acc = fmaf(tanh_fast(qk[g].y + gb[g].y), vp[g].y, acc);
                acc = fmaf(tanh_fast(qk[g].z + gb[g].z), vp[g].z, acc);
                acc = fmaf(tanh_fast(qk[g].w + gb[g].w), vp[g].w, acc);
            }
            acc += __shfl_xor_sync(0xffffffffu, acc, 1);
            acc += __shfl_xor_sync(0xffffffffu, acc, 2);
            acc += __shfl_xor_sync(0xffffffffu, acc, 4);
            acc += __shfl_xor_sync(0xffffffffu, acc, 8);
            if (p == 0) s_u[jl] = acc;
        }
        __syncthreads();

        // phase B (warp 0): logits, fixed-shift expsum + gumbel argmax
        if (t < 32) {
            float lg = masked ? -1e9f : 10.0f * tanh_fast(s_u[t]);
            float ex = __expf(lg - 10.0f);                // fixed shift K=10
            float sc = lg + gv;
            int   si = t;
            float sl = lg;
#pragma unroll
            for (int o = 16; o; o >>= 1) {
                float ov = __shfl_xor_sync(0xffffffffu, sc, o);
                int   oi = __shfl_xor_sync(0xffffffffu, si, o);
                float ol = __shfl_xor_sync(0xffffffffu, sl, o);
                ex += __shfl_xor_sync(0xffffffffu, ex, o);
                if (ov > sc || (ov == sc && oi < si)) { sc = ov; si = oi; sl = ol; }
            }
            // all lanes hold final (sc,si,sl,ex); lanes 0..7 fan out to all ranks
            if (t < 8) {
                uint32_t loc = (i & 1) ? slot_base1 : slot_base0;
                uint32_t rem = mapa_rank(loc, (uint32_t)t);
                st_cluster_b64(rem + 0, pack2(sc, __int_as_float(rank * 32 + si)));
                st_cluster_b64(rem + 8, pack2(sl, ex));
            }
        }
        CLUSTER_SYNC();   // all 8 slots visible in every CTA

        // combine (redundant in all threads): winner across ranks
        const float (*sl8)[4] = s_slots[i & 1];
        float bsc = sl8[0][0]; int gidx = __float_as_int(sl8[0][1]);
        float bsl = sl8[0][2];
#pragma unroll
        for (int r = 1; r < 8; r++) {
            float scr = sl8[r][0];
            if (scr > bsc) { bsc = scr; gidx = __float_as_int(sl8[r][1]); bsl = sl8[r][2]; }
        }
        cur = gidx;
        // mask whole 4-node cell of the winner
        amask |= ((gidx >> 2) == (j >> 2)) ? 1 : 0;                       // phase-A map
        if (t < 32) masked |= ((gidx >> 2) == ((rank * 32 + t) >> 2)) ? 1 : 0;  // phase-B map

        // rank0 t0: stash step data; all heavy math deferred to post-loop
        if (rank == 0 && t == 0) {
            s_bsl[i] = bsl;
            s_gsum[i] = sl8[0][3] + sl8[1][3] + sl8[2][3] + sl8[3][3]
                      + sl8[4][3] + sl8[5][3] + sl8[6][3] + sl8[7][3];
            s_act[i] = gidx;
        }

        if (i == 0) {
            // one-time: qbase = base + Gtop[init], Gtop row computed on the fly
            int init_i = gidx;
            int half = t >> 8, tt = t & 255;
            const float* erow = emb + ((size_t)b * 256 + init_i) * 256 + half * 128;
            const float* wrow = g_WvWq + (size_t)half * 128 * 256 + tt;
            float p0 = 0, p1 = 0, p2 = 0, p3 = 0;
            for (int k = 0; k < 128; k += 4) {
                p0 = fmaf(erow[k + 0], wrow[(k + 0) * 256], p0);
                p1 = fmaf(erow[k + 1], wrow[(k + 1) * 256], p1);
                p2 = fmaf(erow[k + 2], wrow[(k + 2) * 256], p2);
                p3 = fmaf(erow[k + 3], wrow[(k + 3) * 256], p3);
            }
            s_part[t] = (p0 + p1) + (p2 + p3);
            __syncthreads();
            if (t < 256)
                s_qbase[t] = g_base[b * 256 + t] + s_part[t] + s_part[t + 256];
            __syncthreads();
        }
    }

    // -------- deferred epilogue (rank 0 only): lp, rw, actions ----------
    if (rank == 0) {
        __syncthreads();
        if (t < MMAX) {
            int gi = s_act[t];
            float term = s_bsl[t] - 10.0f - __logf(s_gsum[t]);
            float rwt = 0.0f;
            if (t > 0) {
                int pi = s_act[t - 1];
                float dx = s_node[gi * 4 + 0] - s_node[pi * 4 + 2];
                float dy = s_node[gi * 4 + 1] - s_node[pi * 4 + 3];
                rwt = sqrtf(dx * dx + dy * dy) + s_cost[pi] + s_cost[gi];
            }
            out[32 + b * MMAX + t] = (float)gi;
            s_red[t] = term;
            s_red[64 + t] = rwt;
        }
        __syncthreads();
        if (t == 0) {
            float lp = 0.0f, rw = 0.0f;
            for (int k = 0; k < MMAX; k++) { lp += s_red[k]; rw += s_red[64 + k]; }
            out[b] = lp; out[16 + b] = rw;
        }
    }
}

extern "C" void kernel_launch(void* const* d_in, const int* in_sizes, int n_in,
                              void* d_out, int out_size) {
    const float* cell_embed = (const float*)d_in[0];
    const float* original_node = (const float*)d_in[1];
    // d_in[2] maze (unused), d_in[3] num_cell (=64)
    const float* costs  = (const float*)d_in[4];
    const float* init_w = (const float*)d_in[5];
    const float* Whc    = (const float*)d_in[6];
    const float* bhc    = (const float*)d_in[7];
    const float* Wv     = (const float*)d_in[8];
    const float* bv     = (const float*)d_in[9];
    const float* Wq     = (const float*)d_in[10];
    const float* Wk     = (const float*)d_in[11];
    const float* vptr   = (const float*)d_in[12];
    float* out = (float*)d_out;

    dummy_kernel<<<1, 32>>>();   // shifts ncu -s5 capture onto decode_kernel
    k1_kernel<<<1120, 256>>>(Wv, Wq, cell_embed);
    k2_kernel<<<529, 256>>>(cell_embed, Wk, init_w, Whc, bhc, bv, Wq);
    decode_kernel<<<128, 512>>>(original_node, costs, vptr, cell_embed, out);
}